// round 1
// baseline (speedup 1.0000x reference)
#include <cuda_runtime.h>

#define BB 32
#define PP 65536
#define TT 16
#define NB 2048
#define IPT 16

// ---------------- device scratch (no allocations allowed) ----------------
__device__ float              g_overlap[BB][PP];       // best IoU per prior
__device__ unsigned char      g_tidx[BB][PP];          // best truth idx per prior
__device__ unsigned int       g_mine[BB][PP];          // float bits of loss_c_mine
__device__ unsigned long long g_bestprior[BB][TT];     // packed (iou_bits<<32)|~p
__device__ int                g_h1c[BB][NB];
__device__ int                g_h2c[BB][NB];
__device__ int                g_h3c[BB][NB];
__device__ int                g_poscnt[BB];
__device__ double             g_posloss[BB];           // sum loss_c over positives
__device__ double             g_lossl;                 // global smooth-L1 sum
__device__ unsigned int       g_prefix[BB];
__device__ int                g_R[BB];
__device__ int                g_K[BB];
__device__ unsigned int       g_Tbits[BB];
__device__ double             g_sumgt[BB];
__device__ int                g_cntgt[BB];

// ---------------- K0: zero accumulators ----------------
__global__ void __launch_bounds__(256) k_zero() {
    int g = blockIdx.x * blockDim.x + threadIdx.x;
    int stride = gridDim.x * blockDim.x;
    for (int i = g; i < BB * NB; i += stride) {
        ((int*)g_h1c)[i] = 0;
        ((int*)g_h2c)[i] = 0;
        ((int*)g_h3c)[i] = 0;
    }
    for (int i = g; i < BB * TT; i += stride)
        ((unsigned long long*)g_bestprior)[i] = 0ull;
    if (g < BB) {
        g_poscnt[g] = 0;
        g_posloss[g] = 0.0;
        g_sumgt[g] = 0.0;
        g_cntgt[g] = 0;
    }
    if (g == 0) g_lossl = 0.0;
}

// ---------------- K1: matching ----------------
__global__ void __launch_bounds__(256) k_match(const float4* __restrict__ priors,
                                               const float*  __restrict__ targets) {
    int b = blockIdx.y;
    int p = blockIdx.x * 256 + threadIdx.x;
    int tid = threadIdx.x;
    __shared__ float4 tr[TT];
    __shared__ float areaA[TT];
    __shared__ unsigned long long sbest[TT];
    if (tid < TT) {
        const float* tb = targets + (b * TT + tid) * 5;
        float4 v = make_float4(tb[0], tb[1], tb[2], tb[3]);
        tr[tid] = v;
        areaA[tid] = (v.z - v.x) * (v.w - v.y);
        sbest[tid] = 0ull;
    }
    __syncthreads();

    float4 pr = priors[p];
    float hx = pr.z * 0.5f, hy = pr.w * 0.5f;
    float bx0 = pr.x - hx, by0 = pr.y - hy, bx1 = pr.x + hx, by1 = pr.y + hy;
    float areaB = pr.z * pr.w;
    float best = -1.0f;
    int bi = 0;
#pragma unroll
    for (int t = 0; t < TT; t++) {
        float4 a = tr[t];
        float w = fminf(a.z, bx1) - fmaxf(a.x, bx0);
        float h = fminf(a.w, by1) - fmaxf(a.y, by0);
        w = fmaxf(w, 0.0f);
        h = fmaxf(h, 0.0f);
        float inter = w * h;
        float iou = inter / (areaA[t] + areaB - inter);
        if (iou > best) { best = iou; bi = t; }   // strict > = first-index argmax over t
        // packed key: larger iou wins; tie -> smaller p wins (first index)
        unsigned long long pk =
            (((unsigned long long)__float_as_uint(iou)) << 32) |
            (unsigned long long)(0xFFFFFFFFu - (unsigned)p);
#pragma unroll
        for (int o = 16; o > 0; o >>= 1) {
            unsigned long long other = __shfl_down_sync(0xFFFFFFFFu, pk, o);
            if (other > pk) pk = other;
        }
        if ((tid & 31) == 0) atomicMax(&sbest[t], pk);
    }
    g_overlap[b][p] = best;
    g_tidx[b][p] = (unsigned char)bi;
    __syncthreads();
    if (tid < TT) atomicMax(&g_bestprior[b][tid], sbest[tid]);
}

// ---------------- K2: best-prior override (sequential t, last-wins) ----------------
__global__ void k_override() {
    int b = threadIdx.x;
    if (b >= BB) return;
    for (int t = 0; t < TT; t++) {
        unsigned long long pk = g_bestprior[b][t];
        unsigned p = 0xFFFFFFFFu - (unsigned)(pk & 0xFFFFFFFFull);
        g_overlap[b][p] = 2.0f;
        g_tidx[b][p] = (unsigned char)t;
    }
}

// ---------------- K3: per-prior losses + level-1 histogram ----------------
__global__ void __launch_bounds__(256) k_main(const float4* __restrict__ loc,
                                              const float2* __restrict__ conf,
                                              const float4* __restrict__ priors,
                                              const float*  __restrict__ targets) {
    int b = blockIdx.y;
    int tid = threadIdx.x;
    __shared__ int sc[NB];
    __shared__ float4 tr[TT];
    for (int i = tid; i < NB; i += 256) sc[i] = 0;
    if (tid < TT) {
        const float* tb = targets + (b * TT + tid) * 5;
        tr[tid] = make_float4(tb[0], tb[1], tb[2], tb[3]);
    }
    __syncthreads();

    float lossl = 0.0f;
    float ploss = 0.0f;
    int pcnt = 0;
    int pbase = blockIdx.x * (256 * IPT);
#pragma unroll
    for (int i = 0; i < IPT; i++) {
        int p = pbase + i * 256 + tid;
        float ov = g_overlap[b][p];
        bool pos = !(ov < 0.5f);
        float2 c = conf[b * PP + p];
        float m = fmaxf(c.x, c.y);
        float lse = m + log1pf(expf(-fabsf(c.x - c.y)));
        float lc = lse - (pos ? c.y : c.x);      // >= 0
        float mv = pos ? 0.0f : lc;
        unsigned bits = __float_as_uint(mv);
        g_mine[b][p] = bits;
        atomicAdd(&sc[bits >> 21], 1);
        if (pos) {
            pcnt++;
            ploss += lc;
            int ti = g_tidx[b][p];
            float4 a = tr[ti];
            float4 pr = priors[p];
            float gx = ((a.x + a.z) * 0.5f - pr.x) / (0.1f * pr.z);
            float gy = ((a.y + a.w) * 0.5f - pr.y) / (0.1f * pr.w);
            float gw = logf((a.z - a.x) / pr.z) / 0.2f;
            float gh = logf((a.w - a.y) / pr.w) / 0.2f;
            float4 ld = loc[b * PP + p];
            float d0 = fabsf(ld.x - gx), d1 = fabsf(ld.y - gy);
            float d2 = fabsf(ld.z - gw), d3 = fabsf(ld.w - gh);
            lossl += (d0 < 1.0f ? 0.5f * d0 * d0 : d0 - 0.5f);
            lossl += (d1 < 1.0f ? 0.5f * d1 * d1 : d1 - 0.5f);
            lossl += (d2 < 1.0f ? 0.5f * d2 * d2 : d2 - 0.5f);
            lossl += (d3 < 1.0f ? 0.5f * d3 * d3 : d3 - 0.5f);
        }
    }
#pragma unroll
    for (int o = 16; o > 0; o >>= 1) {
        lossl += __shfl_down_sync(0xFFFFFFFFu, lossl, o);
        ploss += __shfl_down_sync(0xFFFFFFFFu, ploss, o);
        pcnt  += __shfl_down_sync(0xFFFFFFFFu, pcnt, o);
    }
    if ((tid & 31) == 0) {
        if (lossl != 0.0f) atomicAdd(&g_lossl, (double)lossl);
        if (pcnt) atomicAdd(&g_poscnt[b], pcnt);
        if (ploss != 0.0f) atomicAdd(&g_posloss[b], (double)ploss);
    }
    __syncthreads();
    for (int i = tid; i < NB; i += 256) {
        int cv = sc[i];
        if (cv) atomicAdd(&g_h1c[b][i], cv);
    }
}

// ---------------- filtered histograms (levels 2 and 3) ----------------
__global__ void __launch_bounds__(256) k_hist_filter(int level) {
    int b = blockIdx.y;
    int tid = threadIdx.x;
    __shared__ int sc[NB];
    for (int i = tid; i < NB; i += 256) sc[i] = 0;
    __syncthreads();
    unsigned pref = g_prefix[b];
    int pbase = blockIdx.x * (256 * IPT);
#pragma unroll
    for (int i = 0; i < IPT; i++) {
        unsigned bits = g_mine[b][pbase + i * 256 + tid];
        unsigned key, bin;
        if (level == 1) { key = bits >> 21; bin = (bits >> 10) & 0x7FFu; }
        else            { key = bits >> 10; bin = bits & 0x3FFu; }
        if (key == pref) atomicAdd(&sc[bin], 1);
    }
    __syncthreads();
    int* gc = (level == 1) ? g_h2c[b] : g_h3c[b];
    for (int i = tid; i < NB; i += 256)
        if (sc[i]) atomicAdd(&gc[i], sc[i]);
}

// ---------------- descending radix-select scan ----------------
__global__ void __launch_bounds__(256) k_scan(int level) {
    int b = blockIdx.x;
    int tid = threadIdx.x;
    const int* cnt = (level == 0) ? g_h1c[b] : (level == 1) ? g_h2c[b] : g_h3c[b];
    __shared__ int tcnt[256];
    __shared__ int epc[256];
    int lc_[8];
    int c = 0;
    int base = tid * 8;
#pragma unroll
    for (int k = 0; k < 8; k++) {
        int idx = NB - 1 - (base + k);
        lc_[k] = cnt[idx];
        c += lc_[k];
    }
    tcnt[tid] = c;
    __syncthreads();
    if (tid == 0) {
        int rc = 0;
        for (int i = 0; i < 256; i++) { epc[i] = rc; rc += tcnt[i]; }
    }
    __syncthreads();
    int R;
    if (level == 0) {
        int np = g_poscnt[b];
        int k3 = 3 * np;
        R = (k3 < PP - 1) ? k3 : (PP - 1);
        if (tid == 0) g_K[b] = R;
    } else {
        R = g_R[b];
    }
    if (epc[tid] < R && R <= epc[tid] + c) {
        int rc = epc[tid];
#pragma unroll
        for (int k = 0; k < 8; k++) {
            int idx = NB - 1 - (base + k);
            if (rc + lc_[k] >= R) {
                if (level == 0)      { g_prefix[b] = (unsigned)idx; g_R[b] = R - rc; }
                else if (level == 1) { g_prefix[b] = (g_prefix[b] << 11) | (unsigned)idx; g_R[b] = R - rc; }
                else                 { g_Tbits[b] = (g_prefix[b] << 10) | (unsigned)idx; }
                break;
            }
            rc += lc_[k];
        }
    }
}

// ---------------- sum of values strictly greater than threshold ----------------
__global__ void __launch_bounds__(256) k_topsum() {
    int b = blockIdx.y;
    int tid = threadIdx.x;
    unsigned Tb = g_Tbits[b];
    double s = 0.0;
    int cg = 0;
    int pbase = blockIdx.x * (256 * IPT);
#pragma unroll
    for (int i = 0; i < IPT; i++) {
        unsigned bits = g_mine[b][pbase + i * 256 + tid];
        if (bits > Tb) { s += (double)__uint_as_float(bits); cg++; }
    }
#pragma unroll
    for (int o = 16; o > 0; o >>= 1) {
        s  += __shfl_down_sync(0xFFFFFFFFu, s, o);
        cg += __shfl_down_sync(0xFFFFFFFFu, cg, o);
    }
    if ((tid & 31) == 0) {
        if (s != 0.0) atomicAdd(&g_sumgt[b], s);
        if (cg) atomicAdd(&g_cntgt[b], cg);
    }
}

// ---------------- final: combine per-batch results ----------------
__global__ void k_final(float* __restrict__ out) {
    int tid = threadIdx.x;   // 32 threads, one per batch
    int np = g_poscnt[tid];
    double T = (double)__uint_as_float(g_Tbits[tid]);
    double topsum = g_sumgt[tid] + (double)(g_K[tid] - g_cntgt[tid]) * T;
    double lc = g_posloss[tid] + topsum;
#pragma unroll
    for (int o = 16; o > 0; o >>= 1) {
        np += __shfl_down_sync(0xFFFFFFFFu, np, o);
        lc += __shfl_down_sync(0xFFFFFFFFu, lc, o);
    }
    if (tid == 0) {
        double N = (double)np;
        out[0] = (float)(g_lossl / N);
        out[1] = (float)(lc / N);
    }
}

// ---------------- launch ----------------
extern "C" void kernel_launch(void* const* d_in, const int* in_sizes, int n_in,
                              void* d_out, int out_size) {
    const float4* loc     = (const float4*)d_in[0];
    const float2* conf    = (const float2*)d_in[1];
    const float4* priors  = (const float4*)d_in[2];
    const float*  targets = (const float*)d_in[3];
    float* out = (float*)d_out;

    k_zero<<<256, 256>>>();
    dim3 gm(PP / 256, BB);
    k_match<<<gm, 256>>>(priors, targets);
    k_override<<<1, BB>>>();
    dim3 g3(PP / (256 * IPT), BB);
    k_main<<<g3, 256>>>(loc, conf, priors, targets);
    k_scan<<<BB, 256>>>(0);
    k_hist_filter<<<g3, 256>>>(1);
    k_scan<<<BB, 256>>>(1);
    k_hist_filter<<<g3, 256>>>(2);
    k_scan<<<BB, 256>>>(2);
    k_topsum<<<g3, 256>>>();
    k_final<<<1, 32>>>(out);
}

// round 2
// speedup vs baseline: 1.1373x; 1.1373x over previous
#include <cuda_runtime.h>

#define BB 32
#define PP 65536
#define TT 16
#define NB 2048
#define BLK 256
#define IPT 16
#define NBLK (PP/(BLK*IPT))   // 16 blocks per batch

// ---------------- device scratch ----------------
__device__ unsigned int       g_mine[BB][PP];
__device__ unsigned long long g_bp[BB][NBLK][TT];
__device__ int    g_h1c[BB][NB];
__device__ int    g_h2c[BB][NB];
__device__ int    g_h3c[BB][NB];
__device__ int    g_poscnt[BB];
__device__ double g_posloss[BB];
__device__ double g_lossl;
__device__ unsigned g_prefix[BB];
__device__ int    g_R[BB];
__device__ double g_sgt[BB];
__device__ double g_topsum[BB];

// ---------------- shared helpers (bit-identical in k1 and k_fix) ----------------
template<bool TRACK>
__device__ __forceinline__ void match_one_prior(
    float4 pr, const float4* tr, const float* cA,
    float& bi, float& bd, int& bti,
    float* ti_, float* td_, unsigned* tp_, unsigned p)
{
    float hx = __fmul_rn(0.5f, pr.z), hy = __fmul_rn(0.5f, pr.w);
    float bx0 = __fsub_rn(pr.x, hx), by0 = __fsub_rn(pr.y, hy);
    float bx1 = __fadd_rn(pr.x, hx), by1 = __fadd_rn(pr.y, hy);
    float areaB = __fmul_rn(__fsub_rn(bx1, bx0), __fsub_rn(by1, by0));
    bi = -1.0f; bd = 1.0f; bti = 0;
#pragma unroll
    for (int t = 0; t < TT; t++) {
        float4 a = tr[t];
        float w = fmaxf(__fsub_rn(fminf(a.z, bx1), fmaxf(a.x, bx0)), 0.0f);
        float h = fmaxf(__fsub_rn(fminf(a.w, by1), fmaxf(a.y, by0)), 0.0f);
        float inter = __fmul_rn(w, h);
        float den = __fsub_rn(__fadd_rn(cA[t], areaB), inter);
        if (__fmul_rn(inter, bd) > __fmul_rn(bi, den)) { bi = inter; bd = den; bti = t; }
        if (TRACK) {
            if (__fmul_rn(inter, td_[t]) > __fmul_rn(ti_[t], den)) {
                ti_[t] = inter; td_[t] = den; tp_[t] = p;
            }
        }
    }
}

__device__ __forceinline__ float lse2(float2 c) {
    return __fadd_rn(fmaxf(c.x, c.y), log1pf(__expf(-fabsf(__fsub_rn(c.x, c.y)))));
}

__device__ __forceinline__ float loc_sl1(float4 ld, float4 a, float4 pr) {
    float gx = ((a.x + a.z) * 0.5f - pr.x) / (0.1f * pr.z);
    float gy = ((a.y + a.w) * 0.5f - pr.y) / (0.1f * pr.w);
    float gw = logf((a.z - a.x) / pr.z) / 0.2f;
    float gh = logf((a.w - a.y) / pr.w) / 0.2f;
    float d0 = fabsf(ld.x - gx), d1 = fabsf(ld.y - gy);
    float d2 = fabsf(ld.z - gw), d3 = fabsf(ld.w - gh);
    return (d0 < 1.f ? 0.5f * d0 * d0 : d0 - 0.5f)
         + (d1 < 1.f ? 0.5f * d1 * d1 : d1 - 0.5f)
         + (d2 < 1.f ? 0.5f * d2 * d2 : d2 - 0.5f)
         + (d3 < 1.f ? 0.5f * d3 * d3 : d3 - 0.5f);
}

// ---------------- K0: zero accumulators ----------------
__global__ void __launch_bounds__(256) k_zero() {
    int g = blockIdx.x * blockDim.x + threadIdx.x;
    int stride = gridDim.x * blockDim.x;
    for (int i = g; i < BB * NB; i += stride) {
        ((int*)g_h1c)[i] = 0;
        ((int*)g_h2c)[i] = 0;
        ((int*)g_h3c)[i] = 0;
    }
    if (g < BB) {
        g_poscnt[g] = 0;
        g_posloss[g] = 0.0;
        g_sgt[g] = 0.0;
    }
    if (g == 0) g_lossl = 0.0;
}

// ---------------- K1: fused match + losses + level-1 histogram ----------------
__global__ void __launch_bounds__(BLK) k1(const float4* __restrict__ loc,
                                          const float2* __restrict__ conf,
                                          const float4* __restrict__ priors,
                                          const float*  __restrict__ targets) {
    int b = blockIdx.y, tid = threadIdx.x;
    int lane = tid & 31;
    __shared__ float4 tr[TT];
    __shared__ float  cA[TT];
    __shared__ int    sc[NB];
    __shared__ unsigned long long skey[TT];
    for (int i = tid; i < NB; i += BLK) sc[i] = 0;
    if (tid < TT) {
        const float* tb = targets + (b * TT + tid) * 5;
        float4 v = make_float4(tb[0], tb[1], tb[2], tb[3]);
        tr[tid] = v;
        cA[tid] = __fmul_rn(__fsub_rn(v.z, v.x), __fsub_rn(v.w, v.y));
        skey[tid] = 0ull;
    }
    __syncthreads();

    float ti_[TT], td_[TT]; unsigned tp_[TT];
#pragma unroll
    for (int t = 0; t < TT; t++) { ti_[t] = -1.0f; td_[t] = 1.0f; tp_[t] = 0u; }

    float lossl = 0.0f, ploss = 0.0f;
    int pcnt = 0;
    int pbase = blockIdx.x * (BLK * IPT);
#pragma unroll 1
    for (int i = 0; i < IPT; i++) {
        int p = pbase + i * BLK + tid;
        float4 pr = priors[p];
        float bi, bd; int bti;
        match_one_prior<true>(pr, tr, cA, bi, bd, bti, ti_, td_, tp_, (unsigned)p);

        bool pos = (__fmul_rn(2.0f, bi) >= bd);
        float2 c = conf[(size_t)b * PP + p];
        float lse = lse2(c);
        float mv = pos ? 0.0f : __fsub_rn(lse, c.x);
        unsigned bits = __float_as_uint(mv);
        g_mine[b][p] = bits;
        unsigned bin = bits >> 21;
        unsigned peers = __match_any_sync(0xFFFFFFFFu, bin);
        if (lane == __ffs(peers) - 1) atomicAdd(&sc[bin], __popc(peers));
        if (pos) {
            pcnt++;
            ploss += __fsub_rn(lse, c.y);
            lossl += loc_sl1(loc[(size_t)b * PP + p], tr[bti], pr);
        }
    }

    // per-truth candidate: one div per (thread,t), u64 key, warp reduce, shared atomicMax
#pragma unroll
    for (int t = 0; t < TT; t++) {
        float iou = ti_[t] / td_[t];
        unsigned long long key =
            ((unsigned long long)__float_as_uint(iou) << 32) |
            (unsigned long long)(0xFFFFFFFFu - tp_[t]);
#pragma unroll
        for (int o = 16; o > 0; o >>= 1) {
            unsigned long long ok = __shfl_down_sync(0xFFFFFFFFu, key, o);
            if (ok > key) key = ok;
        }
        if (lane == 0) atomicMax(&skey[t], key);
    }

#pragma unroll
    for (int o = 16; o > 0; o >>= 1) {
        lossl += __shfl_down_sync(0xFFFFFFFFu, lossl, o);
        ploss += __shfl_down_sync(0xFFFFFFFFu, ploss, o);
        pcnt  += __shfl_down_sync(0xFFFFFFFFu, pcnt, o);
    }
    if (lane == 0) {
        if (lossl != 0.0f) atomicAdd(&g_lossl, (double)lossl);
        if (pcnt) {
            atomicAdd(&g_poscnt[b], pcnt);
            atomicAdd(&g_posloss[b], (double)ploss);
        }
    }
    __syncthreads();
    if (tid < TT) g_bp[b][blockIdx.x][tid] = skey[tid];
    for (int i = tid; i < NB; i += BLK) {
        int cv = sc[i];
        if (cv) atomicAdd(&g_h1c[b][i], cv);
    }
}

// ---------------- K2: fixup for best-prior override (delta corrections) ----------------
__global__ void k_fix(const float4* __restrict__ loc,
                      const float2* __restrict__ conf,
                      const float4* __restrict__ priors,
                      const float*  __restrict__ targets) {
    int b = threadIdx.x;
    if (b >= BB) return;
    float4 tr[TT]; float cA[TT];
#pragma unroll
    for (int t = 0; t < TT; t++) {
        const float* tb = targets + (b * TT + t) * 5;
        float4 v = make_float4(tb[0], tb[1], tb[2], tb[3]);
        tr[t] = v;
        cA[t] = __fmul_rn(__fsub_rn(v.z, v.x), __fsub_rn(v.w, v.y));
    }
    unsigned ps[TT];
#pragma unroll
    for (int t = 0; t < TT; t++) {
        unsigned long long k = 0ull;
        for (int blk = 0; blk < NBLK; blk++) {
            unsigned long long v = g_bp[b][blk][t];
            if (v > k) k = v;
        }
        ps[t] = 0xFFFFFFFFu - (unsigned)(k & 0xFFFFFFFFull);
    }
    for (int t = 0; t < TT; t++) {
        bool last = true;
        for (int t2 = t + 1; t2 < TT; t2++)
            if (ps[t2] == ps[t]) { last = false; break; }
        if (!last) continue;     // last write wins
        unsigned p = ps[t];
        float4 pr = priors[p];
        float bi, bd; int bti;
        match_one_prior<false>(pr, tr, cA, bi, bd, bti, nullptr, nullptr, nullptr, 0u);
        bool pos_old = (__fmul_rn(2.0f, bi) >= bd);
        float2 c = conf[(size_t)b * PP + p];
        float lse = lse2(c);
        float4 ld = loc[(size_t)b * PP + p];
        float sl_new = loc_sl1(ld, tr[t], pr);
        double dl = 0.0;
        if (pos_old) {
            if (bti != t) dl = (double)sl_new - (double)loc_sl1(ld, tr[bti], pr);
        } else {
            dl = (double)sl_new;
            g_poscnt[b] += 1;
            g_posloss[b] += (double)__fsub_rn(lse, c.y);
            float mo = __fsub_rn(lse, c.x);          // bit-identical to k1's mv
            unsigned ob = __float_as_uint(mo) >> 21;
            g_h1c[b][ob] -= 1;
            g_h1c[b][0]  += 1;
            g_mine[b][p] = 0u;
        }
        if (dl != 0.0) atomicAdd(&g_lossl, dl);
    }
}

// ---------------- filtered histograms (levels 1, 2) ----------------
__global__ void __launch_bounds__(256) k_filter(int level) {
    int b = blockIdx.y, tid = threadIdx.x, lane = tid & 31;
    __shared__ int sc[NB];
    for (int i = tid; i < NB; i += 256) sc[i] = 0;
    __syncthreads();
    unsigned pref = g_prefix[b];
    float fsum = 0.0f;
    int pbase = blockIdx.x * (256 * IPT);
#pragma unroll
    for (int i = 0; i < IPT; i++) {
        unsigned bits = g_mine[b][pbase + i * 256 + tid];
        if (level == 1) {
            if ((bits >> 21) == pref) atomicAdd(&sc[(bits >> 10) & 0x7FFu], 1);
        } else {
            unsigned top = bits >> 10;
            if (top == pref) atomicAdd(&sc[bits & 0x3FFu], 1);
            else if (top > pref) fsum += __uint_as_float(bits);
        }
    }
    __syncthreads();
    int* gc = (level == 1) ? g_h2c[b] : g_h3c[b];
    for (int i = tid; i < NB; i += 256)
        if (sc[i]) atomicAdd(&gc[i], sc[i]);
    if (level == 2) {
#pragma unroll
        for (int o = 16; o > 0; o >>= 1)
            fsum += __shfl_down_sync(0xFFFFFFFFu, fsum, o);
        if (lane == 0 && fsum != 0.0f) atomicAdd(&g_sgt[b], (double)fsum);
    }
}

// ---------------- descending radix-select scan (+exact top-K sum at level 2) ----------------
__global__ void __launch_bounds__(256) k_scan(int level) {
    int b = blockIdx.x, tid = threadIdx.x;
    const int* cnt = (level == 0) ? g_h1c[b] : (level == 1) ? g_h2c[b] : g_h3c[b];
    __shared__ int tcnt[256];
    __shared__ int epc[256];
    __shared__ int sR;
    __shared__ unsigned sbin;
    __shared__ double wsum[8];
    int lc_[8];
    int c = 0;
    int base = tid * 8;
#pragma unroll
    for (int k = 0; k < 8; k++) {
        lc_[k] = cnt[NB - 1 - (base + k)];
        c += lc_[k];
    }
    tcnt[tid] = c;
    __syncthreads();
    if (tid == 0) {
        int rc = 0;
        for (int i = 0; i < 256; i++) { epc[i] = rc; rc += tcnt[i]; }
    }
    __syncthreads();
    int R;
    if (level == 0) {
        int k3 = 3 * g_poscnt[b];
        R = (k3 < PP - 1) ? k3 : (PP - 1);
    } else {
        R = g_R[b];
    }
    if (epc[tid] < R && R <= epc[tid] + c) {
        int rc = epc[tid];
#pragma unroll
        for (int k = 0; k < 8; k++) {
            int idx = NB - 1 - (base + k);
            if (rc + lc_[k] >= R) {
                if (level == 0)      { g_prefix[b] = (unsigned)idx; g_R[b] = R - rc; }
                else if (level == 1) { g_prefix[b] = (g_prefix[b] << 11) | (unsigned)idx; g_R[b] = R - rc; }
                else                 { sbin = (unsigned)idx; sR = R - rc; }
                break;
            }
            rc += lc_[k];
        }
    }
    if (level == 2) {
        __syncthreads();
        unsigned pref = g_prefix[b];
        unsigned s3 = sbin;
        int R3 = sR;
        double s = 0.0;
#pragma unroll
        for (int k = 0; k < 8; k++) {
            unsigned idx = (unsigned)(NB - 1 - (base + k));
            if (idx > s3 && lc_[k])
                s += (double)lc_[k] * (double)__uint_as_float((pref << 10) | idx);
        }
#pragma unroll
        for (int o = 16; o > 0; o >>= 1)
            s += __shfl_down_sync(0xFFFFFFFFu, s, o);
        if ((tid & 31) == 0) wsum[tid >> 5] = s;
        __syncthreads();
        if (tid == 0) {
            double tot = 0.0;
            for (int w = 0; w < 8; w++) tot += wsum[w];
            g_topsum[b] = g_sgt[b] + tot +
                          (double)R3 * (double)__uint_as_float((pref << 10) | s3);
        }
    }
}

// ---------------- final combine ----------------
__global__ void k_final(float* __restrict__ out) {
    int tid = threadIdx.x;   // 32 threads, one per batch
    int np = g_poscnt[tid];
    double lc = g_posloss[tid] + g_topsum[tid];
#pragma unroll
    for (int o = 16; o > 0; o >>= 1) {
        np += __shfl_down_sync(0xFFFFFFFFu, np, o);
        lc += __shfl_down_sync(0xFFFFFFFFu, lc, o);
    }
    if (tid == 0) {
        double N = (double)np;
        out[0] = (float)(g_lossl / N);
        out[1] = (float)(lc / N);
    }
}

// ---------------- launch ----------------
extern "C" void kernel_launch(void* const* d_in, const int* in_sizes, int n_in,
                              void* d_out, int out_size) {
    const float4* loc     = (const float4*)d_in[0];
    const float2* conf    = (const float2*)d_in[1];
    const float4* priors  = (const float4*)d_in[2];
    const float*  targets = (const float*)d_in[3];
    float* out = (float*)d_out;

    k_zero<<<256, 256>>>();
    dim3 g1(NBLK, BB);
    k1<<<g1, BLK>>>(loc, conf, priors, targets);
    k_fix<<<1, BB>>>(loc, conf, priors, targets);
    k_scan<<<BB, 256>>>(0);
    dim3 gf(PP / (256 * IPT), BB);
    k_filter<<<gf, 256>>>(1);
    k_scan<<<BB, 256>>>(1);
    k_filter<<<gf, 256>>>(2);
    k_scan<<<BB, 256>>>(2);
    k_final<<<1, 32>>>(out);
}